// round 9
// baseline (speedup 1.0000x reference)
#include <cuda_runtime.h>
#include <cuda_bf16.h>
#include <cuda_fp16.h>
#include <cstdint>

#define SQ 2048
#define NB 2
#define NH 16
#define DKH 64
#define DM 1024
#define NBH (NB * NH)

static const size_t XN = (size_t)NB * SQ * DM;    // 4,194,304
static const size_t WN = (size_t)DM * DM;         // 1,048,576
#define AN ((size_t)NBH * SQ * SQ)                // 134,217,728

// ---------------- device scratch (alloc-free) ----------------
__device__ __half        g_xq[XN], g_xk[XN], g_xv[XN];     // fp16 inputs
__device__ __half        g_wqkv[3 * WN];                   // fp16 weights concat [3072,1024]
__device__ float         g_bqkv[3 * DM];                   // concat bias
__device__ __nv_bfloat16 g_wo_hi[WN], g_wo_lo[WN];         // Wo split bf16
__device__ __half        g_qh[XN], g_kh[XN];               // [bh, s, d] fp16
__device__ __half        g_vt[XN];                         // [bh, d, s] fp16
__device__ __nv_bfloat16 g_ctx_hi[XN], g_ctx_lo[XN];       // [b*s, h*d]
__device__ float2 g_stats[(size_t)NBH * 16 * SQ];          // per-tile (max, sumexp)
__device__ float2 g_rowstat[(size_t)NBH * SQ];             // per-row (max, 1/sum)
__device__ float g_att_scratch[AN];
__device__ float g_dummy_out[XN];

// ---------------- helpers ----------------
template <class A, class B> struct is_same_t { static const bool v = false; };
template <class A> struct is_same_t<A, A> { static const bool v = true; };

__device__ __forceinline__ uint32_t smem_u32(const void* p) {
    uint32_t a;
    asm("{ .reg .u64 t; cvta.to.shared.u64 t, %1; cvt.u32.u64 %0, t; }" : "=r"(a) : "l"(p));
    return a;
}
__device__ __forceinline__ void cpa16(uint32_t s, const void* g) {
    asm volatile("cp.async.ca.shared.global [%0], [%1], 16;" :: "r"(s), "l"(g));
}
__device__ __forceinline__ void cpa_commit() { asm volatile("cp.async.commit_group;"); }
template <int N>
__device__ __forceinline__ void cpa_waitg() {
    asm volatile("cp.async.wait_group %0;" :: "n"(N));
}
__device__ __forceinline__ void ldm4(uint32_t d[4], uint32_t addr) {
    asm volatile("ldmatrix.sync.aligned.m8n8.x4.shared.b16 {%0,%1,%2,%3}, [%4];"
                 : "=r"(d[0]), "=r"(d[1]), "=r"(d[2]), "=r"(d[3]) : "r"(addr));
}
template <bool BF16>
__device__ __forceinline__ void mma16816(float c[4], const uint32_t a[4],
                                         uint32_t b0, uint32_t b1) {
    if (BF16)
        asm volatile(
            "mma.sync.aligned.m16n8k16.row.col.f32.bf16.bf16.f32 "
            "{%0,%1,%2,%3}, {%4,%5,%6,%7}, {%8,%9}, {%0,%1,%2,%3};"
            : "+f"(c[0]), "+f"(c[1]), "+f"(c[2]), "+f"(c[3])
            : "r"(a[0]), "r"(a[1]), "r"(a[2]), "r"(a[3]), "r"(b0), "r"(b1));
    else
        asm volatile(
            "mma.sync.aligned.m16n8k16.row.col.f32.f16.f16.f32 "
            "{%0,%1,%2,%3}, {%4,%5,%6,%7}, {%8,%9}, {%0,%1,%2,%3};"
            : "+f"(c[0]), "+f"(c[1]), "+f"(c[2]), "+f"(c[3])
            : "r"(a[0]), "r"(a[1]), "r"(a[2]), "r"(a[3]), "r"(b0), "r"(b1));
}
__device__ __forceinline__ uint32_t pack_bf2(float v0, float v1) {
    __nv_bfloat16 h0 = __float2bfloat16(v0), h1 = __float2bfloat16(v1);
    return (uint32_t)__bfloat16_as_ushort(h0) | ((uint32_t)__bfloat16_as_ushort(h1) << 16);
}
__device__ __forceinline__ uint32_t pack_hf2(float v0, float v1) {
    __half2 h = __floats2half2_rn(v0, v1);
    return *(uint32_t*)&h;
}

// ============================================================
// MMA GEMM: C[128 x BN] = A[128 x K] * B[BN x K]^T  (rows stride K)
// SPLIT=3: (hi,lo) pairs, 3-mma compensated.  SPLIT=1: single mma.
// MODE 2: out proj -> fp32 [m, DM]  (+bias, split-3)
// MODE 3: scores stats only -> per-tile row (max, sumexp)
// MODE 5: merged QKV proj -> q/k fp16 scatter [bh,s,d], v fp16 [bh,d,s]
// ============================================================
template <int BN, int MODE, int SPLIT, int NSTG, typename T>
__global__ __launch_bounds__(256, 2)
void mma_gemm(const T* __restrict__ Ah_g, const T* __restrict__ Al_g,
              const T* __restrict__ Bh_g, const T* __restrict__ Bl_g,
              const float* __restrict__ bias, const int* __restrict__ mask,
              float* __restrict__ outf, uint32_t* __restrict__ ohi,
              uint32_t* __restrict__ olo, uint32_t* __restrict__ ov,
              float2* __restrict__ stats,
              const T* __restrict__ Ak_g, const T* __restrict__ Av_g,
              int K, size_t sAz, size_t sBz)
{
    constexpr bool BF16 = is_same_t<T, __nv_bfloat16>::v;
    constexpr int BM = 128, BK = 32;
    constexpr int ASZ = BM * 80;
    constexpr int BSZ = BN * 80;
    constexpr int NPART = (SPLIT == 3) ? 2 : 1;
    constexpr int OFF_BH = ASZ * NPART;
    constexpr int STG = (ASZ + BSZ) * NPART;
    constexpr int NSPAN = BN / 2;
    constexpr int NT = NSPAN / 8;

    extern __shared__ char smem[];
    const uint32_t sb = smem_u32(smem);
    const int tid = threadIdx.x;
    const int lane = tid & 31, wid = tid >> 5;
    const int wm = wid & 3, wn = wid >> 2;

    const int m0 = blockIdx.y * BM;
    const int n0 = blockIdx.x * BN;
    const int z  = blockIdx.z;
    const int sec = (MODE == 5) ? (n0 >> 10) : 0;

    const T* pAh = Ah_g ? Ah_g + (size_t)z * sAz : nullptr;
    if (MODE == 5) pAh = (sec == 0) ? Ah_g : (sec == 1) ? Ak_g : Av_g;
    const T* pAl = Al_g ? Al_g + (size_t)z * sAz : nullptr;
    const T* pBh = Bh_g + (size_t)z * sBz;
    const T* pBl = Bl_g ? Bl_g + (size_t)z * sBz : nullptr;

    const int NCH = K / BK;

    auto issue = [&](int c, int st) {
        const int kb = c * BK;
        const uint32_t base = sb + st * STG;
#pragma unroll
        for (int j = 0; j < 2; j++) {
            int u = tid + j * 256, r = u >> 2, c8 = u & 3;
            cpa16(base + r * 80 + c8 * 16,
                  pAh + (size_t)(m0 + r) * K + kb + c8 * 8);
            if (SPLIT == 3)
                cpa16(base + ASZ + r * 80 + c8 * 16,
                      pAl + (size_t)(m0 + r) * K + kb + c8 * 8);
        }
#pragma unroll
        for (int j = 0; j < (BN == 128 ? 2 : 1); j++) {
            int u = tid + j * 256, r = u >> 2, c8 = u & 3;
            cpa16(base + OFF_BH + r * 80 + c8 * 16,
                  pBh + (size_t)(n0 + r) * K + kb + c8 * 8);
            if (SPLIT == 3)
                cpa16(base + OFF_BH + BSZ + r * 80 + c8 * 16,
                      pBl + (size_t)(n0 + r) * K + kb + c8 * 8);
        }
    };

    float acc[2][NT][4];
#pragma unroll
    for (int a = 0; a < 2; a++)
#pragma unroll
        for (int b = 0; b < NT; b++)
#pragma unroll
            for (int c = 0; c < 4; c++) acc[a][b][c] = 0.0f;

#pragma unroll
    for (int s = 0; s < NSTG - 1; s++) {
        if (s < NCH) issue(s, s);
        cpa_commit();
    }

    for (int c = 0; c < NCH; c++) {
        const int st = c % NSTG;
        cpa_waitg<NSTG - 2>();
        __syncthreads();
        if (c + NSTG - 1 < NCH) issue(c + NSTG - 1, (c + NSTG - 1) % NSTG);
        cpa_commit();

        const uint32_t aBase = sb + st * STG;
        const uint32_t bBase = aBase + OFF_BH;
#pragma unroll
        for (int ks = 0; ks < 2; ks++) {
            uint32_t ah[2][4], al[2][4];
#pragma unroll
            for (int mt = 0; mt < 2; mt++) {
                uint32_t ad = aBase + (wm * 32 + mt * 16 + (lane & 15)) * 80
                              + ks * 32 + ((lane >> 4) << 4);
                ldm4(ah[mt], ad);
                if (SPLIT == 3) ldm4(al[mt], ad + ASZ);
            }
            const int g = lane >> 3;
            const int nsub = (g >> 1) * 8, khalf = (g & 1) * 16;
#pragma unroll
            for (int ntp = 0; ntp < NT / 2; ntp++) {
                uint32_t bd = bBase
                    + (wn * NSPAN + ntp * 16 + nsub + (lane & 7)) * 80
                    + ks * 32 + khalf;
                uint32_t bh[4];
                ldm4(bh, bd);
#pragma unroll
                for (int mt = 0; mt < 2; mt++) {
                    mma16816<BF16>(acc[mt][2 * ntp],     ah[mt], bh[0], bh[1]);
                    mma16816<BF16>(acc[mt][2 * ntp + 1], ah[mt], bh[2], bh[3]);
                }
                if (SPLIT == 3) {
                    uint32_t bl[4];
                    ldm4(bl, bd + BSZ);
#pragma unroll
                    for (int mt = 0; mt < 2; mt++) {
                        mma16816<BF16>(acc[mt][2 * ntp],     ah[mt], bl[0], bl[1]);
                        mma16816<BF16>(acc[mt][2 * ntp + 1], ah[mt], bl[2], bl[3]);
                        mma16816<BF16>(acc[mt][2 * ntp],     al[mt], bh[0], bh[1]);
                        mma16816<BF16>(acc[mt][2 * ntp + 1], al[mt], bh[2], bh[3]);
                    }
                }
            }
        }
    }
    __syncthreads();

    // ---------------- epilogue ----------------
    float (*sf)[129] = (float(*)[129])smem;        // MODE5-V staging

#pragma unroll
    for (int mt = 0; mt < 2; mt++)
#pragma unroll
        for (int nt = 0; nt < NT; nt++)
#pragma unroll
            for (int hh = 0; hh < 2; hh++) {
                float v0 = acc[mt][nt][hh * 2 + 0];
                float v1 = acc[mt][nt][hh * 2 + 1];
                const int m_loc = wm * 32 + mt * 16 + (lane >> 2) + hh * 8;
                const int n_loc = wn * NSPAN + nt * 8 + (lane & 3) * 2;
                const int gm = m0 + m_loc, gn = n0 + n_loc;

                if (MODE == 2) {
                    v0 += bias[gn]; v1 += bias[gn + 1];
                    *(float2*)&outf[(size_t)gm * DM + gn] = make_float2(v0, v1);
                } else if (MODE == 3) {
                    v0 *= 0.125f; v1 *= 0.125f;
                    const size_t midx = ((size_t)(z >> 4) * SQ + gm) * SQ + gn;
                    int2 mv = *(const int2*)(mask + midx);
                    if (mv.x == 0) v0 = 1e-9f;
                    if (mv.y == 0) v1 = 1e-9f;
                    acc[mt][nt][hh * 2 + 0] = v0;
                    acc[mt][nt][hh * 2 + 1] = v1;
                } else if (MODE == 5) {
                    v0 += bias[gn]; v1 += bias[gn + 1];
                    if (sec < 2) {
                        const int gnl = gn & 1023;
                        const int b = gm >> 11, s = gm & 2047, h = gnl >> 6, d = gnl & 63;
                        const size_t a = ((((size_t)(b * NH + h)) * SQ + s) * DKH + d) >> 1;
                        (sec ? olo : ohi)[a] = pack_hf2(v0, v1);
                    } else {
                        sf[m_loc][n_loc]     = v0;
                        sf[m_loc][n_loc + 1] = v1;
                    }
                }
            }

    if (MODE == 5 && sec == 2) {                   // V transpose -> [bh, d, s]
        __syncthreads();
        const int b = m0 >> 11, s0 = m0 & 2047;
        const int gnl_base = n0 & 1023;
#pragma unroll
        for (int it = 0; it < 16; it++) {
            const int rn = it * 8 + wid;
            const int gnl = gnl_base + rn;
            const int h = gnl >> 6, d = gnl & 63;
            uint32_t* orow = ov + ((((size_t)(b * NH + h)) * DKH + d) * SQ + s0) / 2;
#pragma unroll
            for (int j = 0; j < 2; j++) {
                const int sp = j * 64 + 2 * lane;
                orow[j * 32 + lane] = pack_hf2(sf[sp][rn], sf[sp + 1][rn]);
            }
        }
    }

    if (MODE == 3) {
        float* smax = (float*)smem;                // [2][128]
        float* ssum = smax + 256;
#pragma unroll
        for (int mt = 0; mt < 2; mt++)
#pragma unroll
            for (int hh = 0; hh < 2; hh++) {
                float mx = -1e30f;
#pragma unroll
                for (int nt = 0; nt < NT; nt++)
                    mx = fmaxf(mx, fmaxf(acc[mt][nt][hh * 2], acc[mt][nt][hh * 2 + 1]));
                mx = fmaxf(mx, __shfl_xor_sync(0xffffffffu, mx, 1));
                mx = fmaxf(mx, __shfl_xor_sync(0xffffffffu, mx, 2));
                if ((lane & 3) == 0)
                    smax[wn * 128 + wm * 32 + mt * 16 + hh * 8 + (lane >> 2)] = mx;
            }
        __syncthreads();
#pragma unroll
        for (int mt = 0; mt < 2; mt++)
#pragma unroll
            for (int hh = 0; hh < 2; hh++) {
                const int m_loc = wm * 32 + mt * 16 + hh * 8 + (lane >> 2);
                const float mx = fmaxf(smax[m_loc], smax[128 + m_loc]);
                float sm = 0.0f;
#pragma unroll
                for (int nt = 0; nt < NT; nt++)
                    sm += __expf(acc[mt][nt][hh * 2 + 0] - mx)
                        + __expf(acc[mt][nt][hh * 2 + 1] - mx);
                sm += __shfl_xor_sync(0xffffffffu, sm, 1);
                sm += __shfl_xor_sync(0xffffffffu, sm, 2);
                if ((lane & 3) == 0) ssum[wn * 128 + m_loc] = sm;
            }
        __syncthreads();
        if (tid < 128) {
            stats[((size_t)z * 16 + blockIdx.x) * SQ + m0 + tid] =
                make_float2(fmaxf(smax[tid], smax[128 + tid]),
                            ssum[tid] + ssum[128 + tid]);
        }
    }
}

// ============================================================
// flash_pv: per (bh, 128-q tile): recompute s = QK^T/8, mask,
// p = exp(s - M)*invS (fp32) -> write att; p -> A-frags (reg identity)
// -> PV MMA accumulate; cross-warp reduce; write ctx bf16 hi/lo.
// ============================================================
__global__ __launch_bounds__(256)
void flash_pv(const __half* __restrict__ qh, const __half* __restrict__ kh,
              const __half* __restrict__ vt, const int* __restrict__ mask,
              const float2* __restrict__ rowstat,
              float* __restrict__ att,
              uint32_t* __restrict__ cx_hi, uint32_t* __restrict__ cx_lo)
{
    constexpr int QSZ = 128 * 144;     // [q][64 halves], 144B rows
    constexpr int KSZ = 128 * 144;
    constexpr int VSZ = 64 * 272;      // [d][128 halves], 272B rows
    constexpr int NKT = SQ / 128;      // 16

    extern __shared__ char smem[];
    const uint32_t sb = smem_u32(smem);
    const int tid = threadIdx.x;
    const int lane = tid & 31, wid = tid >> 5;
    const int wm = wid & 3, wn = wid >> 2;

    const int q0 = blockIdx.x * 128;
    const int bh = blockIdx.y;
    const int b = bh >> 4, h = bh & 15;
    const __half* pQ = qh + (size_t)bh * SQ * DKH;
    const __half* pK = kh + (size_t)bh * SQ * DKH;
    const __half* pV = vt + (size_t)bh * DKH * SQ;
    float* pAtt = att + (size_t)bh * SQ * SQ;

    // row stats: thread's 4 q rows (mt, hh)
    float2 rs[2][2];
#pragma unroll
    for (int mt = 0; mt < 2; mt++)
#pragma unroll
        for (int hh = 0; hh < 2; hh++)
            rs[mt][hh] = rowstat[(size_t)bh * SQ + q0 + wm * 32 + mt * 16 + hh * 8 + (lane >> 2)];

    auto issueKV = [&](int kt, int st) {
#pragma unroll
        for (int j = 0; j < 4; j++) {               // K tile [128][64h]
            int u = tid + j * 256, r = u >> 3, c8 = u & 7;
            cpa16(sb + QSZ + st * KSZ + r * 144 + c8 * 16,
                  pK + (size_t)(kt * 128 + r) * DKH + c8 * 8);
        }
#pragma unroll
        for (int j = 0; j < 4; j++) {               // V tile [64][128h]
            int u = tid + j * 256, r = u >> 4, c16 = u & 15;
            cpa16(sb + QSZ + 3 * KSZ + st * VSZ + r * 272 + c16 * 16,
                  pV + (size_t)r * SQ + kt * 128 + c16 * 8);
        }
    };

    // prologue: Q + first two KV stages
#pragma unroll
    for (int j = 0; j < 4; j++) {
        int u = tid + j * 256, r = u >> 3, c8 = u & 7;
        cpa16(sb + r * 144 + c8 * 16, pQ + (size_t)(q0 + r) * DKH + c8 * 8);
    }
    issueKV(0, 0); cpa_commit();
    issueKV(1, 1); cpa_commit();

    float acc_pv[2][8][4];
#pragma unroll
    for (int a = 0; a < 2; a++)
#pragma unroll
        for (int bq = 0; bq < 8; bq++)
#pragma unroll
            for (int c = 0; c < 4; c++) acc_pv[a][bq][c] = 0.0f;

    const int g = lane >> 3;
    const int nsub = (g >> 1) * 8, khalf = (g & 1) * 16;

    for (int kt = 0; kt < NKT; kt++) {
        cpa_waitg<1>();
        __syncthreads();
        if (kt + 2 < NKT) issueKV(kt + 2, (kt + 2) % 3);
        cpa_commit();

        const uint32_t kBase = sb + QSZ + (kt % 3) * KSZ;
        const uint32_t vBase = sb + QSZ + 3 * KSZ + (kt % 3) * VSZ;

        // ---- QK^T: s[2][8][4] ----
        float acc_s[2][8][4];
#pragma unroll
        for (int a = 0; a < 2; a++)
#pragma unroll
            for (int bq = 0; bq < 8; bq++)
#pragma unroll
                for (int c = 0; c < 4; c++) acc_s[a][bq][c] = 0.0f;

#pragma unroll
        for (int kk = 0; kk < 4; kk++) {
            uint32_t ah[2][4];
#pragma unroll
            for (int mt = 0; mt < 2; mt++) {
                uint32_t ad = sb + (wm * 32 + mt * 16 + (lane & 15)) * 144
                              + kk * 32 + ((lane >> 4) << 4);
                ldm4(ah[mt], ad);
            }
#pragma unroll
            for (int ntp = 0; ntp < 4; ntp++) {
                uint32_t bd = kBase + (wn * 64 + ntp * 16 + nsub + (lane & 7)) * 144
                              + kk * 32 + khalf;
                uint32_t bhf[4];
                ldm4(bhf, bd);
#pragma unroll
                for (int mt = 0; mt < 2; mt++) {
                    mma16816<false>(acc_s[mt][2 * ntp],     ah[mt], bhf[0], bhf[1]);
                    mma16816<false>(acc_s[mt][2 * ntp + 1], ah[mt], bhf[2], bhf[3]);
                }
            }
        }

        // ---- mask + softmax-normalize + att write + PV MMA ----
#pragma unroll
        for (int kg = 0; kg < 4; kg++) {
            uint32_t af[2][4];
#pragma unroll
            for (int mt = 0; mt < 2; mt++) {
#pragma unroll
                for (int j = 0; j < 2; j++) {
                    const int nt = 2 * kg + j;
#pragma unroll
                    for (int hh = 0; hh < 2; hh++) {
                        float v0 = acc_s[mt][nt][hh * 2 + 0] * 0.125f;
                        float v1 = acc_s[mt][nt][hh * 2 + 1] * 0.125f;
                        const int gm = q0 + wm * 32 + mt * 16 + hh * 8 + (lane >> 2);
                        const int gk = kt * 128 + wn * 64 + nt * 8 + (lane & 3) * 2;
                        int2 mv = *(const int2*)(mask + ((size_t)b * SQ + gm) * SQ + gk);
                        if (mv.x == 0) v0 = 1e-9f;
                        if (mv.y == 0) v1 = 1e-9f;
                        const float2 r2 = rs[mt][hh];
                        const float p0 = __expf(v0 - r2.x) * r2.y;
                        const float p1 = __expf(v1 - r2.x) * r2.y;
                        *(float2*)&pAtt[(size_t)gm * SQ + gk] = make_float2(p0, p1);
                        af[mt][j * 2 + hh] = pack_hf2(p0, p1);
                    }
                }
            }
#pragma unroll
            for (int ntp = 0; ntp < 4; ntp++) {
                uint32_t bd = vBase + (ntp * 16 + nsub + (lane & 7)) * 272
                              + wn * 128 + kg * 32 + khalf;
                uint32_t bhf[4];
                ldm4(bhf, bd);
#pragma unroll
                for (int mt = 0; mt < 2; mt++) {
                    mma16816<false>(acc_pv[mt][2 * ntp],     af[mt], bhf[0], bhf[1]);
                    mma16816<false>(acc_pv[mt][2 * ntp + 1], af[mt], bhf[2], bhf[3]);
                }
            }
        }
    }

    // ---- cross-warp (wn) reduction + ctx write ----
    __syncthreads();
    float (*red)[66] = (float(*)[66])smem;         // 128 x 66
    if (wn == 1) {
#pragma unroll
        for (int mt = 0; mt < 2; mt++)
#pragma unroll
            for (int nt = 0; nt < 8; nt++)
#pragma unroll
                for (int hh = 0; hh < 2; hh++) {
                    const int m_loc = wm * 32 + mt * 16 + hh * 8 + (lane >> 2);
                    const int d = nt * 8 + (lane & 3) * 2;
                    red[m_loc][d]     = acc_pv[mt][nt][hh * 2 + 0];
                    red[m_loc][d + 1] = acc_pv[mt][nt][hh * 2 + 1];
                }
    }
    __syncthreads();
    if (wn == 0) {
#pragma unroll
        for (int mt = 0; mt < 2; mt++)
#pragma unroll
            for (int nt = 0; nt < 8; nt++)
#pragma unroll
                for (int hh = 0; hh < 2; hh++) {
                    const int m_loc = wm * 32 + mt * 16 + hh * 8 + (lane >> 2);
                    const int d = nt * 8 + (lane & 3) * 2;
                    const float v0 = acc_pv[mt][nt][hh * 2 + 0] + red[m_loc][d];
                    const float v1 = acc_pv[mt][nt][hh * 2 + 1] + red[m_loc][d + 1];
                    const size_t a = (((size_t)(b * SQ + q0 + m_loc)) * DM + h * DKH + d) >> 1;
                    cx_hi[a] = pack_bf2(v0, v1);
                    cx_lo[a] = pack_bf2(v0 - __bfloat162float(__float2bfloat16(v0)),
                                        v1 - __bfloat162float(__float2bfloat16(v1)));
                }
    }
}

// ---------------- combine per-tile stats -> per-row (max, 1/sum) ----------------
__global__ __launch_bounds__(256)
void stats_reduce(const float2* __restrict__ stats, float2* __restrict__ rowstat)
{
    const int idx = blockIdx.x * 256 + threadIdx.x;
    const int bh = idx >> 11, q = idx & 2047;
    float2 t[16];
    float M = -1e30f;
#pragma unroll
    for (int kb = 0; kb < 16; kb++) {
        t[kb] = stats[((size_t)bh * 16 + kb) * SQ + q];
        M = fmaxf(M, t[kb].x);
    }
    float S = 0.0f;
#pragma unroll
    for (int kb = 0; kb < 16; kb++) S += t[kb].y * __expf(t[kb].x - M);
    rowstat[idx] = make_float2(M, 1.0f / S);
}

// ---------------- fp32 -> fp16 (3 tensors in one launch) ----------------
__global__ __launch_bounds__(256)
void cvt_half3(const float* __restrict__ x0, const float* __restrict__ x1,
               const float* __restrict__ x2,
               __half* __restrict__ o0, __half* __restrict__ o1,
               __half* __restrict__ o2, size_t n4)
{
    size_t i = (size_t)blockIdx.x * blockDim.x + threadIdx.x;
    const int sel = (int)(i / n4);
    const size_t j = i - (size_t)sel * n4;
    const float* x = (sel == 0) ? x0 : (sel == 1) ? x1 : x2;
    __half* o = (sel == 0) ? o0 : (sel == 1) ? o1 : o2;
    float4 v = ((const float4*)x)[j];
    __half2 h0 = __floats2half2_rn(v.x, v.y);
    __half2 h1 = __floats2half2_rn(v.z, v.w);
    ((int2*)o)[j] = make_int2(*(int*)&h0, *(int*)&h1);
}

// ---------------- fp32 -> bf16 hi/lo split (Wo only) ----------------
__global__ __launch_bounds__(256)
void cvt_split(const float* __restrict__ x, __nv_bfloat16* __restrict__ hi,
               __nv_bfloat16* __restrict__ lo, size_t n4)
{
    size_t i = (size_t)blockIdx.x * blockDim.x + threadIdx.x;
    if (i >= n4) return;
    float4 v = ((const float4*)x)[i];
    float f[4] = {v.x, v.y, v.z, v.w};
    uint32_t h[4], l[4];
#pragma unroll
    for (int j = 0; j < 4; j++) {
        __nv_bfloat16 hb = __float2bfloat16(f[j]);
        h[j] = (uint32_t)__bfloat16_as_ushort(hb);
        l[j] = (uint32_t)__bfloat16_as_ushort(__float2bfloat16(f[j] - __bfloat162float(hb)));
    }
    ((int2*)hi)[i] = make_int2((int)(h[0] | (h[1] << 16)), (int)(h[2] | (h[3] << 16)));
    ((int2*)lo)[i] = make_int2((int)(l[0] | (l[1] << 16)), (int)(l[2] | (l[3] << 16)));
}

// ---------------- concat bias ----------------
__global__ void concat_bias(const float* a, const float* b, const float* c, float* o)
{
    const int i = blockIdx.x * 256 + threadIdx.x;
    o[i] = (i < 1024) ? a[i] : (i < 2048) ? b[i - 1024] : c[i - 2048];
}

// ============================================================
extern "C" void kernel_launch(void* const* d_in, const int* in_sizes, int n_in,
                              void* d_out, int out_size)
{
    const float* q    = (const float*)d_in[0];
    const float* k    = (const float*)d_in[1];
    const float* v    = (const float*)d_in[2];
    const int*   mask = (const int*)  d_in[3];
    const float* Wq   = (const float*)d_in[4];
    const float* bq   = (const float*)d_in[5];
    const float* Wk   = (const float*)d_in[6];
    const float* bk   = (const float*)d_in[7];
    const float* Wv   = (const float*)d_in[8];
    const float* bv   = (const float*)d_in[9];
    const float* Wo   = (const float*)d_in[10];
    const float* bo   = (const float*)d_in[11];

    __half *xq, *xk, *xv, *wqkv, *qh, *kh, *vt;
    float *bqkv;
    __nv_bfloat16 *wo_hi, *wo_lo, *cx_hi, *cx_lo;
    float *attscr, *dummy;
    float2 *statsp, *rowstatp;
    cudaGetSymbolAddress((void**)&xq, g_xq); cudaGetSymbolAddress((void**)&xk, g_xk);
    cudaGetSymbolAddress((void**)&xv, g_xv);
    cudaGetSymbolAddress((void**)&wqkv, g_wqkv);
    cudaGetSymbolAddress((void**)&bqkv, g_bqkv);
    cudaGetSymbolAddress((void**)&wo_hi, g_wo_hi); cudaGetSymbolAddress((void**)&wo_lo, g_wo_lo);
    cudaGetSymbolAddress((void**)&qh, g_qh); cudaGetSymbolAddress((void**)&kh, g_kh);
    cudaGetSymbolAddress((void**)&vt, g_vt);
    cudaGetSymbolAddress((void**)&cx_hi, g_ctx_hi); cudaGetSymbolAddress((void**)&cx_lo, g_ctx_lo);
    cudaGetSymbolAddress((void**)&attscr, g_att_scratch);
    cudaGetSymbolAddress((void**)&dummy,  g_dummy_out);
    cudaGetSymbolAddress((void**)&statsp, g_stats);
    cudaGetSymbolAddress((void**)&rowstatp, g_rowstat);

    const long OUT_ELEMS = (long)NB * SQ * DM;
    const long ATT_ELEMS = (long)AN;
    float* outp = (float*)d_out;
    float* attp;
    if ((long)out_size >= OUT_ELEMS + ATT_ELEMS)      attp = outp + OUT_ELEMS;
    else if ((long)out_size == ATT_ELEMS) { attp = outp; outp = dummy; }
    else                                               attp = attscr;

    constexpr int SM_P1_128 = 3 * (10240 + 10240);          // 61440
    constexpr int SM_PROJ   = 66048;                         // >= 128*129*4
    constexpr int SM_S3_128 = 2 * ((10240 + 10240) * 2);     // 81920
    constexpr int SM_FLASH  = 128 * 144 + 3 * 128 * 144 + 3 * 64 * 272;  // 125952

    cudaFuncSetAttribute(mma_gemm<128, 5, 1, 3, __half>,
                         cudaFuncAttributeMaxDynamicSharedMemorySize, SM_PROJ);
    cudaFuncSetAttribute(mma_gemm<128, 3, 1, 3, __half>,
                         cudaFuncAttributeMaxDynamicSharedMemorySize, SM_P1_128);
    cudaFuncSetAttribute(mma_gemm<128, 2, 3, 2, __nv_bfloat16>,
                         cudaFuncAttributeMaxDynamicSharedMemorySize, SM_S3_128);
    cudaFuncSetAttribute(flash_pv,
                         cudaFuncAttributeMaxDynamicSharedMemorySize, SM_FLASH);

    // conversions
    cvt_half3<<<(int)(3 * XN / 4 / 256), 256>>>(q, k, v, xq, xk, xv, XN / 4);
    cvt_half3<<<(int)(3 * WN / 4 / 256), 256>>>(Wq, Wk, Wv, wqkv, wqkv + WN,
                                                wqkv + 2 * WN, WN / 4);
    cvt_split<<<(int)(WN / 4 / 256), 256>>>(Wo, wo_hi, wo_lo, WN / 4);
    concat_bias<<<12, 256>>>(bq, bk, bv, bqkv);

    // merged QKV projection (M=4096, N=3072, K=1024)
    mma_gemm<128, 5, 1, 3, __half><<<dim3(24, 32, 1), 256, SM_PROJ>>>(
        xq, nullptr, wqkv, nullptr, bqkv, nullptr, nullptr,
        (uint32_t*)qh, (uint32_t*)kh, (uint32_t*)vt, nullptr,
        xk, xv, DM, 0, 0);

    // pass 1: score stats only
    mma_gemm<128, 3, 1, 3, __half><<<dim3(16, 16, NBH), 256, SM_P1_128>>>(
        qh, nullptr, kh, nullptr, nullptr, mask, nullptr,
        nullptr, nullptr, nullptr, statsp,
        nullptr, nullptr, DKH, (size_t)SQ * DKH, (size_t)SQ * DKH);

    stats_reduce<<<NBH * SQ / 256, 256>>>(statsp, rowstatp);

    // pass 2: fused recompute + normalize + att write + PV
    flash_pv<<<dim3(16, NBH), 256, SM_FLASH>>>(
        qh, kh, vt, mask, rowstatp, attp, (uint32_t*)cx_hi, (uint32_t*)cx_lo);

    // output projection (split-3 bf16)
    mma_gemm<128, 2, 3, 2, __nv_bfloat16><<<dim3(8, 32, 1), 256, SM_S3_128>>>(
        cx_hi, cx_lo, wo_hi, wo_lo, bo, nullptr, outp,
        nullptr, nullptr, nullptr, nullptr,
        nullptr, nullptr, DM, 0, 0);
}

// round 10
// speedup vs baseline: 1.0703x; 1.0703x over previous
#include <cuda_runtime.h>
#include <cuda_bf16.h>
#include <cuda_fp16.h>
#include <cstdint>

#define SQ 2048
#define NB 2
#define NH 16
#define DKH 64
#define DM 1024
#define NBH (NB * NH)

static const size_t XN = (size_t)NB * SQ * DM;    // 4,194,304
static const size_t WN = (size_t)DM * DM;         // 1,048,576
#define AN ((size_t)NBH * SQ * SQ)                // 134,217,728

// ---------------- device scratch (alloc-free) ----------------
__device__ __half        g_xq[XN], g_xk[XN], g_xv[XN];     // fp16 inputs
__device__ __half        g_wqkv[3 * WN];                   // fp16 weights concat [3072,1024]
__device__ float         g_bqkv[3 * DM];                   // concat bias
__device__ __nv_bfloat16 g_wo_hi[WN], g_wo_lo[WN];         // Wo split bf16
__device__ __half        g_qh[XN], g_kh[XN];               // [bh, s, d] fp16
__device__ __half        g_vt[XN];                         // [bh, d, s] fp16
__device__ __nv_bfloat16 g_ctx_hi[XN], g_ctx_lo[XN];       // [b*s, h*d]
__device__ __half        g_pt[AN];                         // p_tile = exp(s - M_tile) fp16
__device__ float2 g_stats[(size_t)NBH * 16 * SQ];          // per-tile (max, sumexp)
__device__ float g_att_scratch[AN];
__device__ float g_dummy_out[XN];

// ---------------- helpers ----------------
template <class A, class B> struct is_same_t { static const bool v = false; };
template <class A> struct is_same_t<A, A> { static const bool v = true; };

__device__ __forceinline__ uint32_t smem_u32(const void* p) {
    uint32_t a;
    asm("{ .reg .u64 t; cvta.to.shared.u64 t, %1; cvt.u32.u64 %0, t; }" : "=r"(a) : "l"(p));
    return a;
}
__device__ __forceinline__ void cpa16(uint32_t s, const void* g) {
    asm volatile("cp.async.ca.shared.global [%0], [%1], 16;" :: "r"(s), "l"(g));
}
__device__ __forceinline__ void cpa_commit() { asm volatile("cp.async.commit_group;"); }
template <int N>
__device__ __forceinline__ void cpa_waitg() {
    asm volatile("cp.async.wait_group %0;" :: "n"(N));
}
__device__ __forceinline__ void ldm4(uint32_t d[4], uint32_t addr) {
    asm volatile("ldmatrix.sync.aligned.m8n8.x4.shared.b16 {%0,%1,%2,%3}, [%4];"
                 : "=r"(d[0]), "=r"(d[1]), "=r"(d[2]), "=r"(d[3]) : "r"(addr));
}
template <bool BF16>
__device__ __forceinline__ void mma16816(float c[4], const uint32_t a[4],
                                         uint32_t b0, uint32_t b1) {
    if (BF16)
        asm volatile(
            "mma.sync.aligned.m16n8k16.row.col.f32.bf16.bf16.f32 "
            "{%0,%1,%2,%3}, {%4,%5,%6,%7}, {%8,%9}, {%0,%1,%2,%3};"
            : "+f"(c[0]), "+f"(c[1]), "+f"(c[2]), "+f"(c[3])
            : "r"(a[0]), "r"(a[1]), "r"(a[2]), "r"(a[3]), "r"(b0), "r"(b1));
    else
        asm volatile(
            "mma.sync.aligned.m16n8k16.row.col.f32.f16.f16.f32 "
            "{%0,%1,%2,%3}, {%4,%5,%6,%7}, {%8,%9}, {%0,%1,%2,%3};"
            : "+f"(c[0]), "+f"(c[1]), "+f"(c[2]), "+f"(c[3])
            : "r"(a[0]), "r"(a[1]), "r"(a[2]), "r"(a[3]), "r"(b0), "r"(b1));
}
__device__ __forceinline__ uint32_t pack_bf2(float v0, float v1) {
    __nv_bfloat16 h0 = __float2bfloat16(v0), h1 = __float2bfloat16(v1);
    return (uint32_t)__bfloat16_as_ushort(h0) | ((uint32_t)__bfloat16_as_ushort(h1) << 16);
}
__device__ __forceinline__ uint32_t pack_hf2(float v0, float v1) {
    __half2 h = __floats2half2_rn(v0, v1);
    return *(uint32_t*)&h;
}

// ============================================================
// MMA GEMM: C[128 x BN] = A[128 x K] * B[BN x K]^T  (rows stride K)
// SPLIT=3: (hi,lo) pairs, 3-mma compensated.  SPLIT=1: single mma.
// MODE 2: out proj -> fp32 [m, DM]  (+bias, split-3)
// MODE 3: scores -> p_t fp16 (coalesced via smem stage) + tile stats
// MODE 4: normalize + PV -> att fp32 (stcs) + bf16 hi/lo ctx
//         (rowstat computed inline from stats)
// MODE 5: merged QKV proj -> q/k fp16 scatter [bh,s,d], v fp16 [bh,d,s]
// ============================================================
template <int BN, int MODE, int SPLIT, int NSTG, typename T>
__global__ __launch_bounds__(256, 2)
void mma_gemm(const T* __restrict__ Ah_g, const T* __restrict__ Al_g,
              const void* __restrict__ Aux_g,
              const T* __restrict__ Bh_g, const T* __restrict__ Bl_g,
              const float* __restrict__ bias, const int* __restrict__ mask,
              float* __restrict__ outf, uint32_t* __restrict__ ohi,
              uint32_t* __restrict__ olo, uint32_t* __restrict__ ov,
              float2* __restrict__ stats,
              const T* __restrict__ Ak_g, const T* __restrict__ Av_g,
              int K, size_t sAz, size_t sBz)
{
    constexpr bool BF16 = is_same_t<T, __nv_bfloat16>::v;
    constexpr int BM = 128, BK = 32;
    constexpr int ASZ = BM * 80;
    constexpr int BSZ = BN * 80;
    constexpr int NPART = (SPLIT == 3) ? 2 : 1;
    constexpr int OFF_BH = ASZ * NPART;
    constexpr int STG = (ASZ + BSZ) * NPART;
    constexpr int NSPAN = BN / 2;
    constexpr int NT = NSPAN / 8;

    extern __shared__ char smem[];
    const uint32_t sb = smem_u32(smem);
    const int tid = threadIdx.x;
    const int lane = tid & 31, wid = tid >> 5;
    const int wm = wid & 3, wn = wid >> 2;

    const int m0 = blockIdx.y * BM;
    const int n0 = blockIdx.x * BN;
    const int z  = blockIdx.z;
    const int sec = (MODE == 5) ? (n0 >> 10) : 0;

    const T* pAh = Ah_g ? Ah_g + (size_t)z * sAz : nullptr;
    if (MODE == 5) pAh = (sec == 0) ? Ah_g : (sec == 1) ? Ak_g : Av_g;
    const T* pAl = Al_g ? Al_g + (size_t)z * sAz : nullptr;
    const __half* pPt = (MODE == 4) ? (const __half*)Aux_g + (size_t)z * sAz : nullptr;
    float* pW = (MODE == 4) ? outf + (size_t)z * sAz : nullptr;
    const T* pBh = Bh_g + (size_t)z * sBz;
    const T* pBl = Bl_g ? Bl_g + (size_t)z * sBz : nullptr;

    const int NCH = K / BK;

    // MODE 4: per-row (max, invS) computed inline from per-tile stats
    float2 rs[4];
    float sc[4];
    int cur_t = -1;
    if (MODE == 4) {
#pragma unroll
        for (int j = 0; j < 4; j++) {
            const int row = m0 + (tid >> 3) + j * 32;
            float M = -1e30f;
            for (int kb = 0; kb < 16; kb++)
                M = fmaxf(M, stats[((size_t)z * 16 + kb) * SQ + row].x);
            float S = 0.0f;
            for (int kb = 0; kb < 16; kb++) {
                const float2 t = stats[((size_t)z * 16 + kb) * SQ + row];
                S += t.y * __expf(t.x - M);
            }
            rs[j] = make_float2(M, 1.0f / S);
        }
    }

    auto issue = [&](int c, int st) {
        const int kb = c * BK;
        const uint32_t base = sb + st * STG;
        if (MODE != 4) {
#pragma unroll
            for (int j = 0; j < 2; j++) {
                int u = tid + j * 256, r = u >> 2, c8 = u & 3;
                cpa16(base + r * 80 + c8 * 16,
                      pAh + (size_t)(m0 + r) * K + kb + c8 * 8);
                if (SPLIT == 3)
                    cpa16(base + ASZ + r * 80 + c8 * 16,
                          pAl + (size_t)(m0 + r) * K + kb + c8 * 8);
            }
        }
#pragma unroll
        for (int j = 0; j < (BN == 128 ? 2 : 1); j++) {
            int u = tid + j * 256, r = u >> 2, c8 = u & 3;
            cpa16(base + OFF_BH + r * 80 + c8 * 16,
                  pBh + (size_t)(n0 + r) * K + kb + c8 * 8);
            if (SPLIT == 3)
                cpa16(base + OFF_BH + BSZ + r * 80 + c8 * 16,
                      pBl + (size_t)(n0 + r) * K + kb + c8 * 8);
        }
    };

    // ----- MODE 4: p_t fp16 loads + scale + att write + fp16 smem store -----
    uint2 rAp[4];
    auto loadA = [&](int c) {
        const int kb = c * BK;
#pragma unroll
        for (int j = 0; j < 4; j++) {
            int u = tid + j * 256, r = u >> 3, c4 = u & 7;
            rAp[j] = *(const uint2*)(pPt + (size_t)(m0 + r) * K + kb + c4 * 4);
        }
    };
    auto storeA = [&](int c) {
        const int st = c % NSTG, kb = c * BK;
        char* base = smem + st * STG;
        const int t = c >> 2;
        if (t != cur_t) {
            cur_t = t;
#pragma unroll
            for (int j = 0; j < 4; j++) {
                const int r = (tid >> 3) + j * 32;
                const float Mt = stats[((size_t)z * 16 + t) * SQ + m0 + r].x;
                sc[j] = __expf(Mt - rs[j].x) * rs[j].y;
            }
        }
#pragma unroll
        for (int j = 0; j < 4; j++) {
            int u = tid + j * 256, r = u >> 3, c4 = u & 7;
            __half2 h01 = *(__half2*)&rAp[j].x;
            __half2 h23 = *(__half2*)&rAp[j].y;
            float4 p;
            p.x = __low2float(h01)  * sc[j];
            p.y = __high2float(h01) * sc[j];
            p.z = __low2float(h23)  * sc[j];
            p.w = __high2float(h23) * sc[j];
            __stcs((float4*)(pW + (size_t)(m0 + r) * K + kb + c4 * 4), p);
            __half2 o0 = __floats2half2_rn(p.x, p.y);
            __half2 o1 = __floats2half2_rn(p.z, p.w);
            *(int2*)(base + r * 80 + c4 * 8) = make_int2(*(int*)&o0, *(int*)&o1);
        }
    };

    float acc[2][NT][4];
#pragma unroll
    for (int a = 0; a < 2; a++)
#pragma unroll
        for (int b = 0; b < NT; b++)
#pragma unroll
            for (int c = 0; c < 4; c++) acc[a][b][c] = 0.0f;

#pragma unroll
    for (int s = 0; s < NSTG - 1; s++) {
        if (s < NCH) issue(s, s);
        cpa_commit();
    }
    if (MODE == 4) { loadA(0); storeA(0); }

    for (int c = 0; c < NCH; c++) {
        const int st = c % NSTG;
        cpa_waitg<NSTG - 2>();
        __syncthreads();
        if (c + NSTG - 1 < NCH) issue(c + NSTG - 1, (c + NSTG - 1) % NSTG);
        cpa_commit();
        if (MODE == 4 && c + 1 < NCH) loadA(c + 1);

        const uint32_t aBase = sb + st * STG;
        const uint32_t bBase = aBase + OFF_BH;
#pragma unroll
        for (int ks = 0; ks < 2; ks++) {
            uint32_t ah[2][4], al[2][4];
#pragma unroll
            for (int mt = 0; mt < 2; mt++) {
                uint32_t ad = aBase + (wm * 32 + mt * 16 + (lane & 15)) * 80
                              + ks * 32 + ((lane >> 4) << 4);
                ldm4(ah[mt], ad);
                if (SPLIT == 3) ldm4(al[mt], ad + ASZ);
            }
            const int g = lane >> 3;
            const int nsub = (g >> 1) * 8, khalf = (g & 1) * 16;
#pragma unroll
            for (int ntp = 0; ntp < NT / 2; ntp++) {
                uint32_t bd = bBase
                    + (wn * NSPAN + ntp * 16 + nsub + (lane & 7)) * 80
                    + ks * 32 + khalf;
                uint32_t bh[4];
                ldm4(bh, bd);
#pragma unroll
                for (int mt = 0; mt < 2; mt++) {
                    mma16816<BF16>(acc[mt][2 * ntp],     ah[mt], bh[0], bh[1]);
                    mma16816<BF16>(acc[mt][2 * ntp + 1], ah[mt], bh[2], bh[3]);
                }
                if (SPLIT == 3) {
                    uint32_t bl[4];
                    ldm4(bl, bd + BSZ);
#pragma unroll
                    for (int mt = 0; mt < 2; mt++) {
                        mma16816<BF16>(acc[mt][2 * ntp],     ah[mt], bl[0], bl[1]);
                        mma16816<BF16>(acc[mt][2 * ntp + 1], ah[mt], bl[2], bl[3]);
                        mma16816<BF16>(acc[mt][2 * ntp],     al[mt], bh[0], bh[1]);
                        mma16816<BF16>(acc[mt][2 * ntp + 1], al[mt], bh[2], bh[3]);
                    }
                }
            }
        }
        if (MODE == 4 && c + 1 < NCH) storeA(c + 1);
    }
    __syncthreads();

    // ---------------- epilogue ----------------
    float (*sf)[129] = (float(*)[129])smem;        // MODE5-V staging

#pragma unroll
    for (int mt = 0; mt < 2; mt++)
#pragma unroll
        for (int nt = 0; nt < NT; nt++)
#pragma unroll
            for (int hh = 0; hh < 2; hh++) {
                float v0 = acc[mt][nt][hh * 2 + 0];
                float v1 = acc[mt][nt][hh * 2 + 1];
                const int m_loc = wm * 32 + mt * 16 + (lane >> 2) + hh * 8;
                const int n_loc = wn * NSPAN + nt * 8 + (lane & 3) * 2;
                const int gm = m0 + m_loc, gn = n0 + n_loc;

                if (MODE == 2) {
                    v0 += bias[gn]; v1 += bias[gn + 1];
                    *(float2*)&outf[(size_t)gm * DM + gn] = make_float2(v0, v1);
                } else if (MODE == 3) {
                    v0 *= 0.125f; v1 *= 0.125f;
                    const size_t midx = ((size_t)(z >> 4) * SQ + gm) * SQ + gn;
                    int2 mv = *(const int2*)(mask + midx);
                    if (mv.x == 0) v0 = 1e-9f;
                    if (mv.y == 0) v1 = 1e-9f;
                    acc[mt][nt][hh * 2 + 0] = v0;
                    acc[mt][nt][hh * 2 + 1] = v1;
                } else if (MODE == 4) {
                    const int b = z >> 4, h = z & 15;
                    const size_t a = (((size_t)(b * SQ + gm)) * DM + h * DKH + gn) >> 1;
                    ohi[a] = pack_bf2(v0, v1);
                    olo[a] = pack_bf2(v0 - __bfloat162float(__float2bfloat16(v0)),
                                      v1 - __bfloat162float(__float2bfloat16(v1)));
                } else if (MODE == 5) {
                    v0 += bias[gn]; v1 += bias[gn + 1];
                    if (sec < 2) {
                        const int gnl = gn & 1023;
                        const int b = gm >> 11, s = gm & 2047, h = gnl >> 6, d = gnl & 63;
                        const size_t a = ((((size_t)(b * NH + h)) * SQ + s) * DKH + d) >> 1;
                        (sec ? olo : ohi)[a] = pack_hf2(v0, v1);
                    } else {
                        sf[m_loc][n_loc]     = v0;
                        sf[m_loc][n_loc + 1] = v1;
                    }
                }
            }

    if (MODE == 5 && sec == 2) {                   // V transpose -> [bh, d, s]
        __syncthreads();
        const int b = m0 >> 11, s0 = m0 & 2047;
        const int gnl_base = n0 & 1023;
#pragma unroll
        for (int it = 0; it < 16; it++) {
            const int rn = it * 8 + wid;
            const int gnl = gnl_base + rn;
            const int h = gnl >> 6, d = gnl & 63;
            uint32_t* orow = ov + ((((size_t)(b * NH + h)) * DKH + d) * SQ + s0) / 2;
#pragma unroll
            for (int j = 0; j < 2; j++) {
                const int sp = j * 64 + 2 * lane;
                orow[j * 32 + lane] = pack_hf2(sf[sp][rn], sf[sp + 1][rn]);
            }
        }
    }

    if (MODE == 3) {
        float* smax = (float*)smem;                       // [2][128]
        float* ssum = smax + 256;
        __half (*stg)[136] = (__half(*)[136])(smem + 2048); // 128 x 136 halves
        // phase 1: per-half row max
#pragma unroll
        for (int mt = 0; mt < 2; mt++)
#pragma unroll
            for (int hh = 0; hh < 2; hh++) {
                float mx = -1e30f;
#pragma unroll
                for (int nt = 0; nt < NT; nt++)
                    mx = fmaxf(mx, fmaxf(acc[mt][nt][hh * 2], acc[mt][nt][hh * 2 + 1]));
                mx = fmaxf(mx, __shfl_xor_sync(0xffffffffu, mx, 1));
                mx = fmaxf(mx, __shfl_xor_sync(0xffffffffu, mx, 2));
                if ((lane & 3) == 0)
                    smax[wn * 128 + wm * 32 + mt * 16 + hh * 8 + (lane >> 2)] = mx;
            }
        __syncthreads();
        // phase 2: combined max -> p_t into smem stage + sums
#pragma unroll
        for (int mt = 0; mt < 2; mt++)
#pragma unroll
            for (int hh = 0; hh < 2; hh++) {
                const int m_loc = wm * 32 + mt * 16 + hh * 8 + (lane >> 2);
                const float mx = fmaxf(smax[m_loc], smax[128 + m_loc]);
                float sm = 0.0f;
#pragma unroll
                for (int nt = 0; nt < NT; nt++) {
                    const float e0 = __expf(acc[mt][nt][hh * 2 + 0] - mx);
                    const float e1 = __expf(acc[mt][nt][hh * 2 + 1] - mx);
                    sm += e0 + e1;
                    const int n_loc = wn * NSPAN + nt * 8 + (lane & 3) * 2;
                    *(uint32_t*)&stg[m_loc][n_loc] = pack_hf2(e0, e1);
                }
                sm += __shfl_xor_sync(0xffffffffu, sm, 1);
                sm += __shfl_xor_sync(0xffffffffu, sm, 2);
                if ((lane & 3) == 0) ssum[wn * 128 + m_loc] = sm;
            }
        __syncthreads();
        if (tid < 128) {
            stats[((size_t)z * 16 + blockIdx.x) * SQ + m0 + tid] =
                make_float2(fmaxf(smax[tid], smax[128 + tid]),
                            ssum[tid] + ssum[128 + tid]);
        }
        // coalesced p_t copy: 128 rows x 128 halves, 16B/lane streaming
        __half* pPtOut = (__half*)ohi;
#pragma unroll
        for (int it = 0; it < 8; it++) {
            const int u = tid + it * 256;
            const int r = u >> 4, c8 = u & 15;
            int4 val = *(int4*)&stg[r][c8 * 8];
            __stcs((int4*)(pPtOut + ((size_t)z * SQ + m0 + r) * SQ + n0 + c8 * 8), val);
        }
    }
}

// ---------------- fp32 -> fp16 (3 tensors in one launch) ----------------
__global__ __launch_bounds__(256)
void cvt_half3(const float* __restrict__ x0, const float* __restrict__ x1,
               const float* __restrict__ x2,
               __half* __restrict__ o0, __half* __restrict__ o1,
               __half* __restrict__ o2, size_t n4)
{
    size_t i = (size_t)blockIdx.x * blockDim.x + threadIdx.x;
    const int sel = (int)(i / n4);
    const size_t j = i - (size_t)sel * n4;
    const float* x = (sel == 0) ? x0 : (sel == 1) ? x1 : x2;
    __half* o = (sel == 0) ? o0 : (sel == 1) ? o1 : o2;
    float4 v = ((const float4*)x)[j];
    __half2 h0 = __floats2half2_rn(v.x, v.y);
    __half2 h1 = __floats2half2_rn(v.z, v.w);
    ((int2*)o)[j] = make_int2(*(int*)&h0, *(int*)&h1);
}

// ---------------- fp32 -> bf16 hi/lo split (Wo only) ----------------
__global__ __launch_bounds__(256)
void cvt_split(const float* __restrict__ x, __nv_bfloat16* __restrict__ hi,
               __nv_bfloat16* __restrict__ lo, size_t n4)
{
    size_t i = (size_t)blockIdx.x * blockDim.x + threadIdx.x;
    if (i >= n4) return;
    float4 v = ((const float4*)x)[i];
    float f[4] = {v.x, v.y, v.z, v.w};
    uint32_t h[4], l[4];
#pragma unroll
    for (int j = 0; j < 4; j++) {
        __nv_bfloat16 hb = __float2bfloat16(f[j]);
        h[j] = (uint32_t)__bfloat16_as_ushort(hb);
        l[j] = (uint32_t)__bfloat16_as_ushort(__float2bfloat16(f[j] - __bfloat162float(hb)));
    }
    ((int2*)hi)[i] = make_int2((int)(h[0] | (h[1] << 16)), (int)(h[2] | (h[3] << 16)));
    ((int2*)lo)[i] = make_int2((int)(l[0] | (l[1] << 16)), (int)(l[2] | (l[3] << 16)));
}

// ---------------- concat bias ----------------
__global__ void concat_bias(const float* a, const float* b, const float* c, float* o)
{
    const int i = blockIdx.x * 256 + threadIdx.x;
    o[i] = (i < 1024) ? a[i] : (i < 2048) ? b[i - 1024] : c[i - 2048];
}

// ============================================================
extern "C" void kernel_launch(void* const* d_in, const int* in_sizes, int n_in,
                              void* d_out, int out_size)
{
    const float* q    = (const float*)d_in[0];
    const float* k    = (const float*)d_in[1];
    const float* v    = (const float*)d_in[2];
    const int*   mask = (const int*)  d_in[3];
    const float* Wq   = (const float*)d_in[4];
    const float* bq   = (const float*)d_in[5];
    const float* Wk   = (const float*)d_in[6];
    const float* bk   = (const float*)d_in[7];
    const float* Wv   = (const float*)d_in[8];
    const float* bv   = (const float*)d_in[9];
    const float* Wo   = (const float*)d_in[10];
    const float* bo   = (const float*)d_in[11];

    __half *xq, *xk, *xv, *wqkv, *qh, *kh, *vt, *pt;
    float *bqkv;
    __nv_bfloat16 *wo_hi, *wo_lo, *cx_hi, *cx_lo;
    float *attscr, *dummy;
    float2 *statsp;
    cudaGetSymbolAddress((void**)&xq, g_xq); cudaGetSymbolAddress((void**)&xk, g_xk);
    cudaGetSymbolAddress((void**)&xv, g_xv);
    cudaGetSymbolAddress((void**)&wqkv, g_wqkv);
    cudaGetSymbolAddress((void**)&bqkv, g_bqkv);
    cudaGetSymbolAddress((void**)&wo_hi, g_wo_hi); cudaGetSymbolAddress((void**)&wo_lo, g_wo_lo);
    cudaGetSymbolAddress((void**)&qh, g_qh); cudaGetSymbolAddress((void**)&kh, g_kh);
    cudaGetSymbolAddress((void**)&vt, g_vt);
    cudaGetSymbolAddress((void**)&pt, g_pt);
    cudaGetSymbolAddress((void**)&cx_hi, g_ctx_hi); cudaGetSymbolAddress((void**)&cx_lo, g_ctx_lo);
    cudaGetSymbolAddress((void**)&attscr, g_att_scratch);
    cudaGetSymbolAddress((void**)&dummy,  g_dummy_out);
    cudaGetSymbolAddress((void**)&statsp, g_stats);

    const long OUT_ELEMS = (long)NB * SQ * DM;
    const long ATT_ELEMS = (long)AN;
    float* outp = (float*)d_out;
    float* attp;
    if ((long)out_size >= OUT_ELEMS + ATT_ELEMS)      attp = outp + OUT_ELEMS;
    else if ((long)out_size == ATT_ELEMS) { attp = outp; outp = dummy; }
    else                                               attp = attscr;

    constexpr int SM_P1_128 = 3 * (10240 + 10240);          // 61440
    constexpr int SM_PROJ   = 66048;                         // >= 128*129*4
    constexpr int SM_PV     = 3 * (10240 + 5120);            // 46080
    constexpr int SM_S3_128 = 2 * ((10240 + 10240) * 2);     // 81920

    cudaFuncSetAttribute(mma_gemm<128, 5, 1, 3, __half>,
                         cudaFuncAttributeMaxDynamicSharedMemorySize, SM_PROJ);
    cudaFuncSetAttribute(mma_gemm<128, 3, 1, 3, __half>,
                         cudaFuncAttributeMaxDynamicSharedMemorySize, SM_P1_128);
    cudaFuncSetAttribute(mma_gemm<64, 4, 1, 3, __half>,
                         cudaFuncAttributeMaxDynamicSharedMemorySize, SM_PV);
    cudaFuncSetAttribute(mma_gemm<128, 2, 3, 2, __nv_bfloat16>,
                         cudaFuncAttributeMaxDynamicSharedMemorySize, SM_S3_128);

    // conversions
    cvt_half3<<<(int)(3 * XN / 4 / 256), 256>>>(q, k, v, xq, xk, xv, XN / 4);
    cvt_half3<<<(int)(3 * WN / 4 / 256), 256>>>(Wq, Wk, Wv, wqkv, wqkv + WN,
                                                wqkv + 2 * WN, WN / 4);
    cvt_split<<<(int)(WN / 4 / 256), 256>>>(Wo, wo_hi, wo_lo, WN / 4);
    concat_bias<<<12, 256>>>(bq, bk, bv, bqkv);

    // merged QKV projection (M=4096, N=3072, K=1024)
    mma_gemm<128, 5, 1, 3, __half><<<dim3(24, 32, 1), 256, SM_PROJ>>>(
        xq, nullptr, nullptr, wqkv, nullptr, bqkv, nullptr, nullptr,
        (uint32_t*)qh, (uint32_t*)kh, (uint32_t*)vt, nullptr,
        xk, xv, DM, 0, 0);

    // scores: p_t fp16 (coalesced) + per-tile row stats
    mma_gemm<128, 3, 1, 3, __half><<<dim3(16, 16, NBH), 256, SM_P1_128>>>(
        qh, nullptr, nullptr, kh, nullptr, nullptr, mask, nullptr,
        (uint32_t*)pt, nullptr, nullptr, statsp,
        nullptr, nullptr, DKH, (size_t)SQ * DKH, (size_t)SQ * DKH);

    // normalize + PV: reads p_t + stats (rowstat inline), writes att fp32 + ctx hi/lo
    mma_gemm<64, 4, 1, 3, __half><<<dim3(1, 16, NBH), 256, SM_PV>>>(
        nullptr, nullptr, pt, vt, nullptr, nullptr, nullptr, attp,
        (uint32_t*)cx_hi, (uint32_t*)cx_lo, nullptr, statsp,
        nullptr, nullptr, SQ, (size_t)SQ * SQ, (size_t)DKH * SQ);

    // output projection (split-3 bf16)
    mma_gemm<128, 2, 3, 2, __nv_bfloat16><<<dim3(8, 32, 1), 256, SM_S3_128>>>(
        cx_hi, cx_lo, nullptr, wo_hi, wo_lo, bo, nullptr, outp,
        nullptr, nullptr, nullptr, nullptr,
        nullptr, nullptr, DM, 0, 0);
}

// round 11
// speedup vs baseline: 1.1095x; 1.0366x over previous
#include <cuda_runtime.h>
#include <cuda_bf16.h>
#include <cuda_fp16.h>
#include <cstdint>

#define SQ 2048
#define NB 2
#define NH 16
#define DKH 64
#define DM 1024
#define NBH (NB * NH)

static const size_t XN = (size_t)NB * SQ * DM;    // 4,194,304
static const size_t WN = (size_t)DM * DM;         // 1,048,576
#define AN ((size_t)NBH * SQ * SQ)                // 134,217,728

// ---------------- device scratch (alloc-free) ----------------
__device__ __half        g_xq[XN], g_xk[XN], g_xv[XN];     // fp16 inputs
__device__ __half        g_wqkv[3 * WN];                   // fp16 weights concat [3072,1024]
__device__ float         g_bqkv[3 * DM];                   // concat bias
__device__ __half        g_wo_hi[WN], g_wo_lo[WN];         // Wo split fp16
__device__ __half        g_qh[XN], g_kh[XN];               // [bh, s, d] fp16
__device__ __half        g_vt[XN];                         // [bh, d, s] fp16
__device__ __half        g_ctx[XN];                        // [b*s, h*d] fp16
__device__ __half        g_pt[AN];                         // p_tile = exp(s - M_tile) fp16
__device__ float2 g_stats[(size_t)NBH * 16 * SQ];          // per-tile (max, sumexp)
__device__ float g_att_scratch[AN];
__device__ float g_dummy_out[XN];

// ---------------- helpers ----------------
template <class A, class B> struct is_same_t { static const bool v = false; };
template <class A> struct is_same_t<A, A> { static const bool v = true; };

__device__ __forceinline__ uint32_t smem_u32(const void* p) {
    uint32_t a;
    asm("{ .reg .u64 t; cvta.to.shared.u64 t, %1; cvt.u32.u64 %0, t; }" : "=r"(a) : "l"(p));
    return a;
}
__device__ __forceinline__ void cpa16(uint32_t s, const void* g) {
    asm volatile("cp.async.ca.shared.global [%0], [%1], 16;" :: "r"(s), "l"(g));
}
__device__ __forceinline__ void cpa_commit() { asm volatile("cp.async.commit_group;"); }
template <int N>
__device__ __forceinline__ void cpa_waitg() {
    asm volatile("cp.async.wait_group %0;" :: "n"(N));
}
__device__ __forceinline__ void ldm4(uint32_t d[4], uint32_t addr) {
    asm volatile("ldmatrix.sync.aligned.m8n8.x4.shared.b16 {%0,%1,%2,%3}, [%4];"
                 : "=r"(d[0]), "=r"(d[1]), "=r"(d[2]), "=r"(d[3]) : "r"(addr));
}
template <bool BF16>
__device__ __forceinline__ void mma16816(float c[4], const uint32_t a[4],
                                         uint32_t b0, uint32_t b1) {
    if (BF16)
        asm volatile(
            "mma.sync.aligned.m16n8k16.row.col.f32.bf16.bf16.f32 "
            "{%0,%1,%2,%3}, {%4,%5,%6,%7}, {%8,%9}, {%0,%1,%2,%3};"
            : "+f"(c[0]), "+f"(c[1]), "+f"(c[2]), "+f"(c[3])
            : "r"(a[0]), "r"(a[1]), "r"(a[2]), "r"(a[3]), "r"(b0), "r"(b1));
    else
        asm volatile(
            "mma.sync.aligned.m16n8k16.row.col.f32.f16.f16.f32 "
            "{%0,%1,%2,%3}, {%4,%5,%6,%7}, {%8,%9}, {%0,%1,%2,%3};"
            : "+f"(c[0]), "+f"(c[1]), "+f"(c[2]), "+f"(c[3])
            : "r"(a[0]), "r"(a[1]), "r"(a[2]), "r"(a[3]), "r"(b0), "r"(b1));
}
__device__ __forceinline__ uint32_t pack_hf2(float v0, float v1) {
    __half2 h = __floats2half2_rn(v0, v1);
    return *(uint32_t*)&h;
}

// ============================================================
// MMA GEMM: C[128 x BN] = A[128 x K] * B[BN x K]^T  (rows stride K)
// SPLIT=1: single mma.  SPLIT=2: B split (hi,lo), 2 mma.
// SPLIT=3: A and B split, 3 mma compensated.
// MODE 2: out proj -> fp32 [m, DM]  (+bias)
// MODE 3: scores -> p_t fp16 (coalesced via smem stage) + tile stats
// MODE 4: normalize + PV -> att fp32 (stcs) + fp16 ctx
//         (rowstat computed inline from stats)
// MODE 5: merged QKV proj -> q/k fp16 scatter [bh,s,d], v fp16 [bh,d,s]
// ============================================================
template <int BN, int MODE, int SPLIT, int NSTG, typename T>
__global__ __launch_bounds__(256, 2)
void mma_gemm(const T* __restrict__ Ah_g, const T* __restrict__ Al_g,
              const void* __restrict__ Aux_g,
              const T* __restrict__ Bh_g, const T* __restrict__ Bl_g,
              const float* __restrict__ bias, const int* __restrict__ mask,
              float* __restrict__ outf, uint32_t* __restrict__ ohi,
              uint32_t* __restrict__ olo, uint32_t* __restrict__ ov,
              float2* __restrict__ stats,
              const T* __restrict__ Ak_g, const T* __restrict__ Av_g,
              int K, size_t sAz, size_t sBz)
{
    constexpr bool BF16 = is_same_t<T, __nv_bfloat16>::v;
    constexpr int BM = 128, BK = 32;
    constexpr int ASZ = BM * 80;
    constexpr int BSZ = BN * 80;
    constexpr int APART = (SPLIT == 3) ? 2 : 1;
    constexpr int BPART = (SPLIT >= 2) ? 2 : 1;
    constexpr int OFF_BH = ASZ * APART;
    constexpr int STG = ASZ * APART + BSZ * BPART;
    constexpr int NSPAN = BN / 2;
    constexpr int NT = NSPAN / 8;

    extern __shared__ char smem[];
    const uint32_t sb = smem_u32(smem);
    const int tid = threadIdx.x;
    const int lane = tid & 31, wid = tid >> 5;
    const int wm = wid & 3, wn = wid >> 2;

    const int m0 = blockIdx.y * BM;
    const int n0 = blockIdx.x * BN;
    const int z  = blockIdx.z;
    const int sec = (MODE == 5) ? (n0 >> 10) : 0;

    const T* pAh = Ah_g ? Ah_g + (size_t)z * sAz : nullptr;
    if (MODE == 5) pAh = (sec == 0) ? Ah_g : (sec == 1) ? Ak_g : Av_g;
    const T* pAl = Al_g ? Al_g + (size_t)z * sAz : nullptr;
    const __half* pPt = (MODE == 4) ? (const __half*)Aux_g + (size_t)z * sAz : nullptr;
    float* pW = (MODE == 4) ? outf + (size_t)z * sAz : nullptr;
    const T* pBh = Bh_g + (size_t)z * sBz;
    const T* pBl = Bl_g ? Bl_g + (size_t)z * sBz : nullptr;

    const int NCH = K / BK;

    // MODE 4: per-row (max, invS) computed inline from per-tile stats
    float2 rs[4];
    float sc[4];
    int cur_t = -1;
    if (MODE == 4) {
#pragma unroll
        for (int j = 0; j < 4; j++) {
            const int row = m0 + (tid >> 3) + j * 32;
            float M = -1e30f;
            for (int kb = 0; kb < 16; kb++)
                M = fmaxf(M, stats[((size_t)z * 16 + kb) * SQ + row].x);
            float S = 0.0f;
            for (int kb = 0; kb < 16; kb++) {
                const float2 t = stats[((size_t)z * 16 + kb) * SQ + row];
                S += t.y * __expf(t.x - M);
            }
            rs[j] = make_float2(M, 1.0f / S);
        }
    }

    auto issue = [&](int c, int st) {
        const int kb = c * BK;
        const uint32_t base = sb + st * STG;
        if (MODE != 4) {
#pragma unroll
            for (int j = 0; j < 2; j++) {
                int u = tid + j * 256, r = u >> 2, c8 = u & 3;
                cpa16(base + r * 80 + c8 * 16,
                      pAh + (size_t)(m0 + r) * K + kb + c8 * 8);
                if (SPLIT == 3)
                    cpa16(base + ASZ + r * 80 + c8 * 16,
                          pAl + (size_t)(m0 + r) * K + kb + c8 * 8);
            }
        }
#pragma unroll
        for (int j = 0; j < (BN == 128 ? 2 : 1); j++) {
            int u = tid + j * 256, r = u >> 2, c8 = u & 3;
            cpa16(base + OFF_BH + r * 80 + c8 * 16,
                  pBh + (size_t)(n0 + r) * K + kb + c8 * 8);
            if (SPLIT >= 2)
                cpa16(base + OFF_BH + BSZ + r * 80 + c8 * 16,
                      pBl + (size_t)(n0 + r) * K + kb + c8 * 8);
        }
    };

    // ----- MODE 4: p_t fp16 loads + scale + att write + fp16 smem store -----
    uint2 rAp[4];
    auto loadA = [&](int c) {
        const int kb = c * BK;
#pragma unroll
        for (int j = 0; j < 4; j++) {
            int u = tid + j * 256, r = u >> 3, c4 = u & 7;
            rAp[j] = *(const uint2*)(pPt + (size_t)(m0 + r) * K + kb + c4 * 4);
        }
    };
    auto storeA = [&](int c) {
        const int st = c % NSTG, kb = c * BK;
        char* base = smem + st * STG;
        const int t = c >> 2;
        if (t != cur_t) {
            cur_t = t;
#pragma unroll
            for (int j = 0; j < 4; j++) {
                const int r = (tid >> 3) + j * 32;
                const float Mt = stats[((size_t)z * 16 + t) * SQ + m0 + r].x;
                sc[j] = __expf(Mt - rs[j].x) * rs[j].y;
            }
        }
#pragma unroll
        for (int j = 0; j < 4; j++) {
            int u = tid + j * 256, r = u >> 3, c4 = u & 7;
            __half2 h01 = *(__half2*)&rAp[j].x;
            __half2 h23 = *(__half2*)&rAp[j].y;
            float4 p;
            p.x = __low2float(h01)  * sc[j];
            p.y = __high2float(h01) * sc[j];
            p.z = __low2float(h23)  * sc[j];
            p.w = __high2float(h23) * sc[j];
            __stcs((float4*)(pW + (size_t)(m0 + r) * K + kb + c4 * 4), p);
            __half2 o0 = __floats2half2_rn(p.x, p.y);
            __half2 o1 = __floats2half2_rn(p.z, p.w);
            *(int2*)(base + r * 80 + c4 * 8) = make_int2(*(int*)&o0, *(int*)&o1);
        }
    };

    float acc[2][NT][4];
#pragma unroll
    for (int a = 0; a < 2; a++)
#pragma unroll
        for (int b = 0; b < NT; b++)
#pragma unroll
            for (int c = 0; c < 4; c++) acc[a][b][c] = 0.0f;

#pragma unroll
    for (int s = 0; s < NSTG - 1; s++) {
        if (s < NCH) issue(s, s);
        cpa_commit();
    }
    if (MODE == 4) { loadA(0); storeA(0); }

    for (int c = 0; c < NCH; c++) {
        const int st = c % NSTG;
        cpa_waitg<NSTG - 2>();
        __syncthreads();
        if (c + NSTG - 1 < NCH) issue(c + NSTG - 1, (c + NSTG - 1) % NSTG);
        cpa_commit();
        if (MODE == 4 && c + 1 < NCH) loadA(c + 1);

        const uint32_t aBase = sb + st * STG;
        const uint32_t bBase = aBase + OFF_BH;
#pragma unroll
        for (int ks = 0; ks < 2; ks++) {
            uint32_t ah[2][4], al[2][4];
#pragma unroll
            for (int mt = 0; mt < 2; mt++) {
                uint32_t ad = aBase + (wm * 32 + mt * 16 + (lane & 15)) * 80
                              + ks * 32 + ((lane >> 4) << 4);
                ldm4(ah[mt], ad);
                if (SPLIT == 3) ldm4(al[mt], ad + ASZ);
            }
            const int g = lane >> 3;
            const int nsub = (g >> 1) * 8, khalf = (g & 1) * 16;
#pragma unroll
            for (int ntp = 0; ntp < NT / 2; ntp++) {
                uint32_t bd = bBase
                    + (wn * NSPAN + ntp * 16 + nsub + (lane & 7)) * 80
                    + ks * 32 + khalf;
                uint32_t bh[4];
                ldm4(bh, bd);
#pragma unroll
                for (int mt = 0; mt < 2; mt++) {
                    mma16816<BF16>(acc[mt][2 * ntp],     ah[mt], bh[0], bh[1]);
                    mma16816<BF16>(acc[mt][2 * ntp + 1], ah[mt], bh[2], bh[3]);
                }
                if (SPLIT >= 2) {
                    uint32_t bl[4];
                    ldm4(bl, bd + BSZ);
#pragma unroll
                    for (int mt = 0; mt < 2; mt++) {
                        mma16816<BF16>(acc[mt][2 * ntp],     ah[mt], bl[0], bl[1]);
                        mma16816<BF16>(acc[mt][2 * ntp + 1], ah[mt], bl[2], bl[3]);
                    }
                    if (SPLIT == 3) {
#pragma unroll
                        for (int mt = 0; mt < 2; mt++) {
                            mma16816<BF16>(acc[mt][2 * ntp],     al[mt], bh[0], bh[1]);
                            mma16816<BF16>(acc[mt][2 * ntp + 1], al[mt], bh[2], bh[3]);
                        }
                    }
                }
            }
        }
        if (MODE == 4 && c + 1 < NCH) storeA(c + 1);
    }
    __syncthreads();

    // ---------------- epilogue ----------------
    float (*sf)[129] = (float(*)[129])smem;        // MODE5-V staging

#pragma unroll
    for (int mt = 0; mt < 2; mt++)
#pragma unroll
        for (int nt = 0; nt < NT; nt++)
#pragma unroll
            for (int hh = 0; hh < 2; hh++) {
                float v0 = acc[mt][nt][hh * 2 + 0];
                float v1 = acc[mt][nt][hh * 2 + 1];
                const int m_loc = wm * 32 + mt * 16 + (lane >> 2) + hh * 8;
                const int n_loc = wn * NSPAN + nt * 8 + (lane & 3) * 2;
                const int gm = m0 + m_loc, gn = n0 + n_loc;

                if (MODE == 2) {
                    v0 += bias[gn]; v1 += bias[gn + 1];
                    *(float2*)&outf[(size_t)gm * DM + gn] = make_float2(v0, v1);
                } else if (MODE == 3) {
                    v0 *= 0.125f; v1 *= 0.125f;
                    const size_t midx = ((size_t)(z >> 4) * SQ + gm) * SQ + gn;
                    int2 mv = *(const int2*)(mask + midx);
                    if (mv.x == 0) v0 = 1e-9f;
                    if (mv.y == 0) v1 = 1e-9f;
                    acc[mt][nt][hh * 2 + 0] = v0;
                    acc[mt][nt][hh * 2 + 1] = v1;
                } else if (MODE == 4) {
                    const int b = z >> 4, h = z & 15;
                    const size_t a = (((size_t)(b * SQ + gm)) * DM + h * DKH + gn) >> 1;
                    ohi[a] = pack_hf2(v0, v1);
                } else if (MODE == 5) {
                    v0 += bias[gn]; v1 += bias[gn + 1];
                    if (sec < 2) {
                        const int gnl = gn & 1023;
                        const int b = gm >> 11, s = gm & 2047, h = gnl >> 6, d = gnl & 63;
                        const size_t a = ((((size_t)(b * NH + h)) * SQ + s) * DKH + d) >> 1;
                        (sec ? olo : ohi)[a] = pack_hf2(v0, v1);
                    } else {
                        sf[m_loc][n_loc]     = v0;
                        sf[m_loc][n_loc + 1] = v1;
                    }
                }
            }

    if (MODE == 5 && sec == 2) {                   // V transpose -> [bh, d, s]
        __syncthreads();
        const int b = m0 >> 11, s0 = m0 & 2047;
        const int gnl_base = n0 & 1023;
#pragma unroll
        for (int it = 0; it < 16; it++) {
            const int rn = it * 8 + wid;
            const int gnl = gnl_base + rn;
            const int h = gnl >> 6, d = gnl & 63;
            uint32_t* orow = ov + ((((size_t)(b * NH + h)) * DKH + d) * SQ + s0) / 2;
#pragma unroll
            for (int j = 0; j < 2; j++) {
                const int sp = j * 64 + 2 * lane;
                orow[j * 32 + lane] = pack_hf2(sf[sp][rn], sf[sp + 1][rn]);
            }
        }
    }

    if (MODE == 3) {
        float* smax = (float*)smem;                       // [2][128]
        float* ssum = smax + 256;
        __half (*stg)[136] = (__half(*)[136])(smem + 2048); // 128 x 136 halves
        // phase 1: per-half row max
#pragma unroll
        for (int mt = 0; mt < 2; mt++)
#pragma unroll
            for (int hh = 0; hh < 2; hh++) {
                float mx = -1e30f;
#pragma unroll
                for (int nt = 0; nt < NT; nt++)
                    mx = fmaxf(mx, fmaxf(acc[mt][nt][hh * 2], acc[mt][nt][hh * 2 + 1]));
                mx = fmaxf(mx, __shfl_xor_sync(0xffffffffu, mx, 1));
                mx = fmaxf(mx, __shfl_xor_sync(0xffffffffu, mx, 2));
                if ((lane & 3) == 0)
                    smax[wn * 128 + wm * 32 + mt * 16 + hh * 8 + (lane >> 2)] = mx;
            }
        __syncthreads();
        // phase 2: combined max -> p_t into smem stage + sums
#pragma unroll
        for (int mt = 0; mt < 2; mt++)
#pragma unroll
            for (int hh = 0; hh < 2; hh++) {
                const int m_loc = wm * 32 + mt * 16 + hh * 8 + (lane >> 2);
                const float mx = fmaxf(smax[m_loc], smax[128 + m_loc]);
                float sm = 0.0f;
#pragma unroll
                for (int nt = 0; nt < NT; nt++) {
                    const float e0 = __expf(acc[mt][nt][hh * 2 + 0] - mx);
                    const float e1 = __expf(acc[mt][nt][hh * 2 + 1] - mx);
                    sm += e0 + e1;
                    const int n_loc = wn * NSPAN + nt * 8 + (lane & 3) * 2;
                    *(uint32_t*)&stg[m_loc][n_loc] = pack_hf2(e0, e1);
                }
                sm += __shfl_xor_sync(0xffffffffu, sm, 1);
                sm += __shfl_xor_sync(0xffffffffu, sm, 2);
                if ((lane & 3) == 0) ssum[wn * 128 + m_loc] = sm;
            }
        __syncthreads();
        if (tid < 128) {
            stats[((size_t)z * 16 + blockIdx.x) * SQ + m0 + tid] =
                make_float2(fmaxf(smax[tid], smax[128 + tid]),
                            ssum[tid] + ssum[128 + tid]);
        }
        // coalesced p_t copy: 128 rows x 128 halves, 16B/lane streaming
        __half* pPtOut = (__half*)ohi;
#pragma unroll
        for (int it = 0; it < 8; it++) {
            const int u = tid + it * 256;
            const int r = u >> 4, c8 = u & 15;
            int4 val = *(int4*)&stg[r][c8 * 8];
            __stcs((int4*)(pPtOut + ((size_t)z * SQ + m0 + r) * SQ + n0 + c8 * 8), val);
        }
    }
}

// ---------------- fp32 -> fp16 (3 tensors in one launch) ----------------
__global__ __launch_bounds__(256)
void cvt_half3(const float* __restrict__ x0, const float* __restrict__ x1,
               const float* __restrict__ x2,
               __half* __restrict__ o0, __half* __restrict__ o1,
               __half* __restrict__ o2, size_t n4)
{
    size_t i = (size_t)blockIdx.x * blockDim.x + threadIdx.x;
    const int sel = (int)(i / n4);
    const size_t j = i - (size_t)sel * n4;
    const float* x = (sel == 0) ? x0 : (sel == 1) ? x1 : x2;
    __half* o = (sel == 0) ? o0 : (sel == 1) ? o1 : o2;
    float4 v = ((const float4*)x)[j];
    __half2 h0 = __floats2half2_rn(v.x, v.y);
    __half2 h1 = __floats2half2_rn(v.z, v.w);
    ((int2*)o)[j] = make_int2(*(int*)&h0, *(int*)&h1);
}

// ---------------- Wo fp16 hi/lo split + bias concat (fused) ----------------
__global__ __launch_bounds__(256)
void cvt_wo_bias(const float* __restrict__ Wo, __half* __restrict__ hi,
                 __half* __restrict__ lo,
                 const float* __restrict__ ba, const float* __restrict__ bb,
                 const float* __restrict__ bc, float* __restrict__ bqkv)
{
    const size_t n4 = WN / 4;
    size_t i = (size_t)blockIdx.x * 256 + threadIdx.x;
    if (i < n4) {
        float4 v = ((const float4*)Wo)[i];
        float f[4] = {v.x, v.y, v.z, v.w};
        uint32_t h[4], l[4];
#pragma unroll
        for (int j = 0; j < 4; j++) {
            __half hb = __float2half_rn(f[j]);
            __half lb = __float2half_rn(f[j] - __half2float(hb));
            h[j] = (uint32_t)__half_as_ushort(hb);
            l[j] = (uint32_t)__half_as_ushort(lb);
        }
        ((int2*)hi)[i] = make_int2((int)(h[0] | (h[1] << 16)), (int)(h[2] | (h[3] << 16)));
        ((int2*)lo)[i] = make_int2((int)(l[0] | (l[1] << 16)), (int)(l[2] | (l[3] << 16)));
    } else {
        const int kk = (int)(i - n4);
        if (kk < 3 * DM)
            bqkv[kk] = (kk < DM) ? ba[kk] : (kk < 2 * DM) ? bb[kk - DM] : bc[kk - 2 * DM];
    }
}

// ============================================================
extern "C" void kernel_launch(void* const* d_in, const int* in_sizes, int n_in,
                              void* d_out, int out_size)
{
    const float* q    = (const float*)d_in[0];
    const float* k    = (const float*)d_in[1];
    const float* v    = (const float*)d_in[2];
    const int*   mask = (const int*)  d_in[3];
    const float* Wq   = (const float*)d_in[4];
    const float* bq   = (const float*)d_in[5];
    const float* Wk   = (const float*)d_in[6];
    const float* bk   = (const float*)d_in[7];
    const float* Wv   = (const float*)d_in[8];
    const float* bv   = (const float*)d_in[9];
    const float* Wo   = (const float*)d_in[10];
    const float* bo   = (const float*)d_in[11];

    __half *xq, *xk, *xv, *wqkv, *qh, *kh, *vt, *pt, *ctx, *wo_hi, *wo_lo;
    float *bqkv;
    float *attscr, *dummy;
    float2 *statsp;
    cudaGetSymbolAddress((void**)&xq, g_xq); cudaGetSymbolAddress((void**)&xk, g_xk);
    cudaGetSymbolAddress((void**)&xv, g_xv);
    cudaGetSymbolAddress((void**)&wqkv, g_wqkv);
    cudaGetSymbolAddress((void**)&bqkv, g_bqkv);
    cudaGetSymbolAddress((void**)&wo_hi, g_wo_hi); cudaGetSymbolAddress((void**)&wo_lo, g_wo_lo);
    cudaGetSymbolAddress((void**)&qh, g_qh); cudaGetSymbolAddress((void**)&kh, g_kh);
    cudaGetSymbolAddress((void**)&vt, g_vt);
    cudaGetSymbolAddress((void**)&pt, g_pt);
    cudaGetSymbolAddress((void**)&ctx, g_ctx);
    cudaGetSymbolAddress((void**)&attscr, g_att_scratch);
    cudaGetSymbolAddress((void**)&dummy,  g_dummy_out);
    cudaGetSymbolAddress((void**)&statsp, g_stats);

    const long OUT_ELEMS = (long)NB * SQ * DM;
    const long ATT_ELEMS = (long)AN;
    float* outp = (float*)d_out;
    float* attp;
    if ((long)out_size >= OUT_ELEMS + ATT_ELEMS)      attp = outp + OUT_ELEMS;
    else if ((long)out_size == ATT_ELEMS) { attp = outp; outp = dummy; }
    else                                               attp = attscr;

    constexpr int SM_P1_128 = 3 * (10240 + 10240);          // 61440
    constexpr int SM_PROJ   = 66048;                         // >= 128*129*4
    constexpr int SM_PV     = 3 * (10240 + 5120);            // 46080
    constexpr int SM_S2_128 = 3 * (10240 + 2 * 10240);       // 92160

    cudaFuncSetAttribute(mma_gemm<128, 5, 1, 3, __half>,
                         cudaFuncAttributeMaxDynamicSharedMemorySize, SM_PROJ);
    cudaFuncSetAttribute(mma_gemm<128, 3, 1, 3, __half>,
                         cudaFuncAttributeMaxDynamicSharedMemorySize, SM_P1_128);
    cudaFuncSetAttribute(mma_gemm<64, 4, 1, 3, __half>,
                         cudaFuncAttributeMaxDynamicSharedMemorySize, SM_PV);
    cudaFuncSetAttribute(mma_gemm<128, 2, 2, 3, __half>,
                         cudaFuncAttributeMaxDynamicSharedMemorySize, SM_S2_128);

    // conversions
    cvt_half3<<<(int)(3 * XN / 4 / 256), 256>>>(q, k, v, xq, xk, xv, XN / 4);
    cvt_half3<<<(int)(3 * WN / 4 / 256), 256>>>(Wq, Wk, Wv, wqkv, wqkv + WN,
                                                wqkv + 2 * WN, WN / 4);
    cvt_wo_bias<<<(int)(WN / 4 / 256) + 12, 256>>>(Wo, wo_hi, wo_lo, bq, bk, bv, bqkv);

    // merged QKV projection (M=4096, N=3072, K=1024)
    mma_gemm<128, 5, 1, 3, __half><<<dim3(24, 32, 1), 256, SM_PROJ>>>(
        xq, nullptr, nullptr, wqkv, nullptr, bqkv, nullptr, nullptr,
        (uint32_t*)qh, (uint32_t*)kh, (uint32_t*)vt, nullptr,
        xk, xv, DM, 0, 0);

    // scores: p_t fp16 (coalesced) + per-tile row stats
    mma_gemm<128, 3, 1, 3, __half><<<dim3(16, 16, NBH), 256, SM_P1_128>>>(
        qh, nullptr, nullptr, kh, nullptr, nullptr, mask, nullptr,
        (uint32_t*)pt, nullptr, nullptr, statsp,
        nullptr, nullptr, DKH, (size_t)SQ * DKH, (size_t)SQ * DKH);

    // normalize + PV: reads p_t + stats (rowstat inline), writes att fp32 + fp16 ctx
    mma_gemm<64, 4, 1, 3, __half><<<dim3(1, 16, NBH), 256, SM_PV>>>(
        nullptr, nullptr, pt, vt, nullptr, nullptr, nullptr, attp,
        (uint32_t*)ctx, nullptr, nullptr, statsp,
        nullptr, nullptr, SQ, (size_t)SQ * SQ, (size_t)DKH * SQ);

    // output projection: fp16 ctx single x fp16 Wo split-2 (2 MMAs)
    mma_gemm<128, 2, 2, 3, __half><<<dim3(8, 32, 1), 256, SM_S2_128>>>(
        ctx, nullptr, nullptr, wo_hi, wo_lo, bo, nullptr, outp,
        nullptr, nullptr, nullptr, nullptr,
        nullptr, nullptr, DM, 0, 0);
}